// round 11
// baseline (speedup 1.0000x reference)
#include <cuda_runtime.h>

// SSIM loss, (32,1,512,512) fp32. Single fused kernel, vertical-first FIR.
// R9 = R8 + column-pair packed phase 1: even-aligned LDG.64 loads ARE the
//      f32x2 operands (no packs), all 3 channels packed FIR, transpose to
//      (x,y)-packed smem in the epilogue. Staging shifted 1 col left so
//      global column pairs are 8B-aligned. VC=76, PIT=77.

#define IMG   512
#define TW    64
#define TH    32
#define VC    76          // staged cols (colE .. colE+75), colE = col0-1 even
#define NPAIR 38
#define PIT   77          // f32 stride 13 mod 32 (bijective); u64 26r distinct/16
#define GX    8
#define GY    16
#define GZ    32
#define NBLK  (GX * GY * GZ)   // 4096

__device__ float        g_partials[NBLK];
__device__ unsigned int g_count;     // zero-init; self-resets

// normalized 1D Gaussian, K=11, sigma=1.5
#define W0 0.00102838f
#define W1 0.00759876f
#define W2 0.03600077f
#define W3 0.10936060f
#define W4 0.21300553f
#define W5 0.26601172f

#define FMA2(d, a, b, c) \
    asm("fma.rn.f32x2 %0, %1, %2, %3;" : "=l"(d) : "l"(a), "l"(b), "l"(c))
#define MUL2(d, a, b) \
    asm("mul.rn.f32x2 %0, %1, %2;" : "=l"(d) : "l"(a), "l"(b))
#define UNPK(lo, hi, v) \
    asm("mov.b64 {%0, %1}, %2;" : "=f"(lo), "=f"(hi) : "l"(v))
#define PK(v, lo, hi) \
    asm("mov.b64 %0, {%1, %2};" : "=l"(v) : "f"(lo), "f"(hi))

__device__ __forceinline__ unsigned long long pk2(float w) {
    unsigned long long r;
    asm("mov.b64 %0, {%1, %1};" : "=l"(r) : "f"(w));
    return r;
}

__global__ __launch_bounds__(256, 5)
void ssim_fused_kernel(const float* __restrict__ X, const float* __restrict__ Y,
                       float* __restrict__ out)
{
    __shared__ unsigned long long vxy[TH][PIT];  // packed (x,y) v-conv 19.7KB
    __shared__ float              vp [TH][PIT];  // v-conv of x*y        9.9KB
    __shared__ float              wsum[8];
    __shared__ int                s_last;

    const unsigned long long p0 = pk2(W0), p1 = pk2(W1), p2 = pk2(W2),
                             p3 = pk2(W3), p4 = pk2(W4), p5 = pk2(W5);
    const unsigned long long WP[11] = {p0,p1,p2,p3,p4,p5,p4,p3,p2,p1,p0};
    const float WGs[11] = {W0, W1, W2, W3, W4, W5, W4, W3, W2, W1, W0};

    const int tid  = threadIdx.x;
    const int img  = blockIdx.z;
    const int row0 = blockIdx.y * TH - 5;
    const int colE = blockIdx.x * TW - 6;   // even; staged col s = global - colE

    const float* __restrict__ Xi = X + (size_t)img * IMG * IMG;
    const float* __restrict__ Yi = Y + (size_t)img * IMG * IMG;

    const bool rowsafe = (row0 >= 0) && (row0 + TH + 9 < IMG);

    // ---- phase 1: packed vertical FIR from GLOBAL: 304 items ----
    // item = (column-pair u of 38, 4-row group g of 8); reads 14 rows as LDG.64.
    #pragma unroll 1
    for (int i = tid; i < NPAIR * 8; i += 256) {
        const int u  = i % NPAIR;
        const int g  = i / NPAIR;
        const int gc = colE + 2 * u;        // even; pair never straddles 0/512
        const int rb = row0 + 4 * g;        // first input row

        unsigned long long ax[4], ay[4], ap[4];
        #pragma unroll
        for (int j = 0; j < 4; j++) { ax[j] = 0ull; ay[j] = 0ull; ap[j] = 0ull; }

        if ((unsigned)gc < (unsigned)IMG) {
            const float2* __restrict__ px = (const float2*)(Xi + gc);
            const float2* __restrict__ py = (const float2*)(Yi + gc);
            if (rowsafe) {
                #pragma unroll
                for (int m = 0; m < 14; m++) {
                    const int off = ((rb + m) * IMG) >> 1;
                    float2 xf = __ldg(px + off);
                    float2 yf = __ldg(py + off);
                    unsigned long long xv = *(unsigned long long*)&xf;
                    unsigned long long yv = *(unsigned long long*)&yf;
                    unsigned long long pv;
                    MUL2(pv, xv, yv);
                    #pragma unroll
                    for (int j = 0; j < 4; j++) {
                        const int k = m - j;
                        if (k >= 0 && k <= 10) {
                            FMA2(ax[j], xv, WP[k], ax[j]);
                            FMA2(ay[j], yv, WP[k], ay[j]);
                            FMA2(ap[j], pv, WP[k], ap[j]);
                        }
                    }
                }
            } else {
                #pragma unroll
                for (int m = 0; m < 14; m++) {
                    const int gr = rb + m;
                    unsigned long long xv = 0ull, yv = 0ull;
                    if ((unsigned)gr < (unsigned)IMG) {
                        float2 xf = __ldg(px + ((gr * IMG) >> 1));
                        float2 yf = __ldg(py + ((gr * IMG) >> 1));
                        xv = *(unsigned long long*)&xf;
                        yv = *(unsigned long long*)&yf;
                    }
                    unsigned long long pv;
                    MUL2(pv, xv, yv);
                    #pragma unroll
                    for (int j = 0; j < 4; j++) {
                        const int k = m - j;
                        if (k >= 0 && k <= 10) {
                            FMA2(ax[j], xv, WP[k], ax[j]);
                            FMA2(ay[j], yv, WP[k], ay[j]);
                            FMA2(ap[j], pv, WP[k], ap[j]);
                        }
                    }
                }
            }
        }
        // epilogue: transpose (c0,c1) pairs -> (x,y) packed per column
        const int vr = 4 * g;
        const int s0 = 2 * u;
        #pragma unroll
        for (int j = 0; j < 4; j++) {
            float x0, x1, y0, y1, q0, q1;
            UNPK(x0, x1, ax[j]);
            UNPK(y0, y1, ay[j]);
            UNPK(q0, q1, ap[j]);
            unsigned long long v0, v1;
            PK(v0, x0, y0);
            PK(v1, x1, y1);
            vxy[vr + j][s0]     = v0;
            vxy[vr + j][s0 + 1] = v1;
            vp [vr + j][s0]     = q0;
            vp [vr + j][s0 + 1] = q1;
        }
    }
    __syncthreads();

    // ---- phase 2: horizontal FIR from smem + SSIM: 256 items ----
    // item = (row r of 32, colgroup o of 8); 8 outputs, window s = c0..c0+17.
    const float C1 = 0.0001f, C2 = 0.0009f;
    float lsum = 0.0f;
    {
        const int r  = tid & 31;
        const int c0 = (tid >> 5) * 8 + 1;   // +1: staging shifted one col left

        unsigned long long acc2[8];
        float accp[8];
        #pragma unroll
        for (int j = 0; j < 8; j++) { acc2[j] = 0ull; accp[j] = 0.0f; }

        #pragma unroll
        for (int m = 0; m < 18; m++) {
            unsigned long long v = vxy[r][c0 + m];
            float pm = vp[r][c0 + m];
            #pragma unroll
            for (int j = 0; j < 8; j++) {
                const int k = m - j;
                if (k >= 0 && k <= 10) {
                    FMA2(acc2[j], v, WP[k], acc2[j]);
                    accp[j] = fmaf(WGs[k], pm, accp[j]);
                }
            }
        }
        #pragma unroll
        for (int j = 0; j < 8; j++) {
            float mu1, mu2;
            UNPK(mu1, mu2, acc2[j]);
            float m12 = mu1 * mu2;
            float sig = accp[j] - m12;
            float sq  = mu1 * mu1 + mu2 * mu2;
            float num = (2.0f * m12 + C1) * (2.0f * sig + C2);
            float den = (sq + C1) * (sq + C2);
            lsum += __fdividef(num, den);
        }
    }

    // ---------------- block reduction ----------------
    #pragma unroll
    for (int off = 16; off > 0; off >>= 1)
        lsum += __shfl_xor_sync(0xFFFFFFFFu, lsum, off);
    if ((tid & 31) == 0) wsum[tid >> 5] = lsum;
    __syncthreads();
    if (tid == 0) {
        float v = 0.0f;
        #pragma unroll
        for (int w = 0; w < 8; w++) v += wsum[w];
        int bid = blockIdx.x + GX * (blockIdx.y + GY * blockIdx.z);
        g_partials[bid] = v;
        __threadfence();
        unsigned int ticket = atomicAdd(&g_count, 1u);
        s_last = (ticket == NBLK - 1);
    }
    __syncthreads();

    // ---------------- last block: final reduction ----------------
    if (s_last) {
        float s = 0.0f;
        #pragma unroll 4
        for (int i = tid; i < NBLK; i += 256)
            s += *((volatile float*)&g_partials[i]);
        #pragma unroll
        for (int off = 16; off > 0; off >>= 1)
            s += __shfl_xor_sync(0xFFFFFFFFu, s, off);
        __syncthreads();
        if ((tid & 31) == 0) wsum[tid >> 5] = s;
        __syncthreads();
        if (tid == 0) {
            float v = 0.0f;
            #pragma unroll
            for (int w = 0; w < 8; w++) v += wsum[w];
            out[0]  = v * (1.0f / 8388608.0f);
            g_count = 0;
        }
    }
}

extern "C" void kernel_launch(void* const* d_in, const int* in_sizes, int n_in,
                              void* d_out, int out_size)
{
    (void)in_sizes; (void)n_in; (void)out_size;
    const float* X_gt   = (const float*)d_in[0];
    const float* X_pred = (const float*)d_in[1];
    float* out = (float*)d_out;

    dim3 grid(GX, GY, GZ);
    ssim_fused_kernel<<<grid, 256>>>(X_gt, X_pred, out);
}

// round 12
// speedup vs baseline: 1.0949x; 1.0949x over previous
#include <cuda_runtime.h>

// SSIM loss, (32,1,512,512) fp32. Single fused kernel, vertical-first FIR.
// R10 = R8 (best: packed u64 staging of xy v-conv, scalar product channel)
//       + __launch_bounds__(256,6): 6 blocks/SM to absorb LDS/LDG latency and
//       the phase-1 item imbalance (296 items / 256 threads).
// R9 lesson kept: 8-row groups are mandatory (vertical read amplification
// 18/8=2.25; shrinking groups inflates LDG bytes and regresses).

#define IMG   512
#define TW    64
#define TH    32
#define VC    74          // v-conv cols staged (TW + 10)
#define PIT   75          // pitch: f32 stride 11 mod 32; u64 stride 22 mod 32 (both clean)
#define GX    8
#define GY    16
#define GZ    32
#define NBLK  (GX * GY * GZ)   // 4096

__device__ float        g_partials[NBLK];
__device__ unsigned int g_count;     // zero-init; self-resets

// normalized 1D Gaussian, K=11, sigma=1.5
#define W0 0.00102838f
#define W1 0.00759876f
#define W2 0.03600077f
#define W3 0.10936060f
#define W4 0.21300553f
#define W5 0.26601172f

#define FMA2(d, a, b, c) \
    asm("fma.rn.f32x2 %0, %1, %2, %3;" : "=l"(d) : "l"(a), "l"(b), "l"(c))
#define UNPK(lo, hi, v) \
    asm("mov.b64 {%0, %1}, %2;" : "=f"(lo), "=f"(hi) : "l"(v))
#define PK(v, lo, hi) \
    asm("mov.b64 %0, {%1, %2};" : "=l"(v) : "f"(lo), "f"(hi))

__device__ __forceinline__ unsigned long long pk2(float w) {
    unsigned long long r;
    asm("mov.b64 %0, {%1, %1};" : "=l"(r) : "f"(w));
    return r;
}

__global__ __launch_bounds__(256, 6)
void ssim_fused_kernel(const float* __restrict__ X, const float* __restrict__ Y,
                       float* __restrict__ out)
{
    __shared__ unsigned long long vxy[TH][PIT];  // packed v-conv (x,y) 18.75KB
    __shared__ float              vp [TH][PIT];  // v-conv of x*y        9.4KB
    __shared__ float              wsum[8];
    __shared__ int                s_last;

    const float WGs[11] = {W0, W1, W2, W3, W4, W5, W4, W3, W2, W1, W0};
    const unsigned long long p0 = pk2(W0), p1 = pk2(W1), p2 = pk2(W2),
                             p3 = pk2(W3), p4 = pk2(W4), p5 = pk2(W5);
    const unsigned long long WP[11] = {p0,p1,p2,p3,p4,p5,p4,p3,p2,p1,p0};

    const int tid  = threadIdx.x;
    const int img  = blockIdx.z;
    const int row0 = blockIdx.y * TH - 5;
    const int col0 = blockIdx.x * TW - 5;

    const float* __restrict__ Xi = X + (size_t)img * IMG * IMG;
    const float* __restrict__ Yi = Y + (size_t)img * IMG * IMG;

    const bool rowsafe = (row0 >= 0) && (row0 + TH + 9 < IMG);

    // ---- phase 1: vertical streaming FIR from GLOBAL: 296 items ----
    // item = (column c of 74, rowgroup g of 4); 8 outputs, reads 18 rows.
    #pragma unroll 1
    for (int i = tid; i < VC * 4; i += 256) {
        const int c  = i % VC;
        const int g  = i / VC;
        const int gc = col0 + c;
        const int rb = row0 + g * 8;

        unsigned long long acc2[8];
        float accp[8];
        #pragma unroll
        for (int j = 0; j < 8; j++) { acc2[j] = 0ull; accp[j] = 0.0f; }

        if ((unsigned)gc < (unsigned)IMG) {
            const float* __restrict__ px = Xi + gc;
            const float* __restrict__ py = Yi + gc;
            if (rowsafe) {
                #pragma unroll
                for (int m = 0; m < 18; m++) {
                    const int off = (rb + m) * IMG;
                    float xv = __ldg(px + off);
                    float yv = __ldg(py + off);
                    unsigned long long v;
                    PK(v, xv, yv);
                    float pm = xv * yv;
                    #pragma unroll
                    for (int j = 0; j < 8; j++) {
                        const int k = m - j;
                        if (k >= 0 && k <= 10) {
                            FMA2(acc2[j], v, WP[k], acc2[j]);
                            accp[j] = fmaf(WGs[k], pm, accp[j]);
                        }
                    }
                }
            } else {
                #pragma unroll
                for (int m = 0; m < 18; m++) {
                    const int gr = rb + m;
                    float xv = 0.0f, yv = 0.0f;
                    if ((unsigned)gr < (unsigned)IMG) {
                        xv = __ldg(px + gr * IMG);
                        yv = __ldg(py + gr * IMG);
                    }
                    unsigned long long v;
                    PK(v, xv, yv);
                    float pm = xv * yv;
                    #pragma unroll
                    for (int j = 0; j < 8; j++) {
                        const int k = m - j;
                        if (k >= 0 && k <= 10) {
                            FMA2(acc2[j], v, WP[k], acc2[j]);
                            accp[j] = fmaf(WGs[k], pm, accp[j]);
                        }
                    }
                }
            }
        }
        const int vr = g * 8;
        #pragma unroll
        for (int j = 0; j < 8; j++) {
            vxy[vr + j][c] = acc2[j];    // packed store, no unpack
            vp [vr + j][c] = accp[j];
        }
    }
    __syncthreads();

    // ---- phase 2: horizontal FIR from smem + SSIM: 256 items ----
    // item = (row r of 32, colgroup o of 8); 8 outputs, reads 18 cols.
    const float C1 = 0.0001f, C2 = 0.0009f;
    float lsum = 0.0f;
    {
        const int r  = tid & 31;
        const int c0 = (tid >> 5) * 8;

        unsigned long long acc2[8];
        float accp[8];
        #pragma unroll
        for (int j = 0; j < 8; j++) { acc2[j] = 0ull; accp[j] = 0.0f; }

        #pragma unroll
        for (int m = 0; m < 18; m++) {
            unsigned long long v = vxy[r][c0 + m];   // LDS.64, feeds FMA2 directly
            float pm = vp[r][c0 + m];
            #pragma unroll
            for (int j = 0; j < 8; j++) {
                const int k = m - j;
                if (k >= 0 && k <= 10) {
                    FMA2(acc2[j], v, WP[k], acc2[j]);
                    accp[j] = fmaf(WGs[k], pm, accp[j]);
                }
            }
        }
        #pragma unroll
        for (int j = 0; j < 8; j++) {
            float mu1, mu2;
            UNPK(mu1, mu2, acc2[j]);
            float m12 = mu1 * mu2;
            float sig = accp[j] - m12;
            float sq  = mu1 * mu1 + mu2 * mu2;
            float num = (2.0f * m12 + C1) * (2.0f * sig + C2);
            float den = (sq + C1) * (sq + C2);
            lsum += __fdividef(num, den);
        }
    }

    // ---------------- block reduction ----------------
    #pragma unroll
    for (int off = 16; off > 0; off >>= 1)
        lsum += __shfl_xor_sync(0xFFFFFFFFu, lsum, off);
    if ((tid & 31) == 0) wsum[tid >> 5] = lsum;
    __syncthreads();
    if (tid == 0) {
        float v = 0.0f;
        #pragma unroll
        for (int w = 0; w < 8; w++) v += wsum[w];
        int bid = blockIdx.x + GX * (blockIdx.y + GY * blockIdx.z);
        g_partials[bid] = v;
        __threadfence();
        unsigned int ticket = atomicAdd(&g_count, 1u);
        s_last = (ticket == NBLK - 1);
    }
    __syncthreads();

    // ---------------- last block: final reduction ----------------
    if (s_last) {
        float s = 0.0f;
        #pragma unroll 4
        for (int i = tid; i < NBLK; i += 256)
            s += *((volatile float*)&g_partials[i]);
        #pragma unroll
        for (int off = 16; off > 0; off >>= 1)
            s += __shfl_xor_sync(0xFFFFFFFFu, s, off);
        __syncthreads();
        if ((tid & 31) == 0) wsum[tid >> 5] = s;
        __syncthreads();
        if (tid == 0) {
            float v = 0.0f;
            #pragma unroll
            for (int w = 0; w < 8; w++) v += wsum[w];
            out[0]  = v * (1.0f / 8388608.0f);
            g_count = 0;
        }
    }
}

extern "C" void kernel_launch(void* const* d_in, const int* in_sizes, int n_in,
                              void* d_out, int out_size)
{
    (void)in_sizes; (void)n_in; (void)out_size;
    const float* X_gt   = (const float*)d_in[0];
    const float* X_pred = (const float*)d_in[1];
    float* out = (float*)d_out;

    dim3 grid(GX, GY, GZ);
    ssim_fused_kernel<<<grid, 256>>>(X_gt, X_pred, out);
}

// round 13
// speedup vs baseline: 1.4308x; 1.3067x over previous
#include <cuda_runtime.h>

// SSIM loss, (32,1,512,512) fp32. Single fused kernel, vertical-first FIR.
// R11: phase 1 = streaming ring FIR (11 accumulators, 32 outputs per column
//      from 42 reads -> 1.31 loads/output vs R8's 2.25). Tile 128x32,
//      128-thread blocks, 4 blocks/SM. Phase 2 unchanged from R8 (packed u64
//      xy plane, scalar product channel). Fused last-block mean.

#define IMG   512
#define TW    128
#define TH    32
#define VC    138         // staged cols (TW + 10)
#define PIT   139         // 139 mod 32 = 11 (f32), mod 16 = 11 (u64): conflict-free
#define NT    128
#define GX    4
#define GY    16
#define GZ    32
#define NBLK  (GX * GY * GZ)   // 2048

__device__ float        g_partials[NBLK];
__device__ unsigned int g_count;     // zero-init; self-resets

// normalized 1D Gaussian, K=11, sigma=1.5
#define W0 0.00102838f
#define W1 0.00759876f
#define W2 0.03600077f
#define W3 0.10936060f
#define W4 0.21300553f
#define W5 0.26601172f

#define FMA2(d, a, b, c) \
    asm("fma.rn.f32x2 %0, %1, %2, %3;" : "=l"(d) : "l"(a), "l"(b), "l"(c))
#define MUL2(d, a, b) \
    asm("mul.rn.f32x2 %0, %1, %2;" : "=l"(d) : "l"(a), "l"(b))
#define UNPK(lo, hi, v) \
    asm("mov.b64 {%0, %1}, %2;" : "=f"(lo), "=f"(hi) : "l"(v))
#define PK(v, lo, hi) \
    asm("mov.b64 %0, {%1, %2};" : "=l"(v) : "f"(lo), "f"(hi))

__device__ __forceinline__ unsigned long long pk2(float w) {
    unsigned long long r;
    asm("mov.b64 %0, {%1, %1};" : "=l"(r) : "f"(w));
    return r;
}

__global__ __launch_bounds__(NT, 4)
void ssim_fused_kernel(const float* __restrict__ X, const float* __restrict__ Y,
                       float* __restrict__ out)
{
    __shared__ unsigned long long vxy[TH][PIT];  // packed v-conv (x,y) 35.6KB
    __shared__ float              vp [TH][PIT];  // v-conv of x*y       17.8KB
    __shared__ float              wsum[4];
    __shared__ int                s_last;

    const float WGs[11] = {W0, W1, W2, W3, W4, W5, W4, W3, W2, W1, W0};
    const unsigned long long p0 = pk2(W0), p1 = pk2(W1), p2 = pk2(W2),
                             p3 = pk2(W3), p4 = pk2(W4), p5 = pk2(W5);
    const unsigned long long WP[11] = {p0,p1,p2,p3,p4,p5,p4,p3,p2,p1,p0};

    const int tid  = threadIdx.x;
    const int img  = blockIdx.z;
    const int row0 = blockIdx.y * TH - 5;
    const int col0 = blockIdx.x * TW - 5;

    const float* __restrict__ Xi = X + (size_t)img * IMG * IMG;
    const float* __restrict__ Yi = Y + (size_t)img * IMG * IMG;

    const bool rowsafe = (row0 >= 0) && (row0 + TH + 9 < IMG);

    // ---- phase 1: streaming vertical FIR, ring of 11 accumulators ----
    // item = column c (138 items); reads 42 rows, writes 32 outputs.
    #pragma unroll 1
    for (int c = tid; c < VC; c += NT) {
        const int gc = col0 + c;
        if ((unsigned)gc < (unsigned)IMG) {
            const float* __restrict__ px = Xi + gc;
            const float* __restrict__ py = Yi + gc;

            unsigned long long axy[11];
            float ap[11];

            #pragma unroll
            for (int m = 0; m < TH + 10; m++) {
                const int gr = row0 + m;
                const bool rok = rowsafe || ((unsigned)gr < (unsigned)IMG);
                float xv = rok ? __ldg(px + gr * IMG) : 0.0f;
                float yv = rok ? __ldg(py + gr * IMG) : 0.0f;
                unsigned long long v;
                PK(v, xv, yv);
                float pm = xv * yv;

                // input row m contributes tap k=m-o to outputs o in [m-10, m] & [0,31]
                #pragma unroll
                for (int o = 0; o < TH; o++) {
                    if (o <= m && m <= o + 10) {
                        const int k = m - o;
                        if (k == 0) {             // first tap: init (== fma into 0)
                            MUL2(axy[o % 11], v, WP[0]);
                            ap[o % 11] = WGs[0] * pm;
                        } else {
                            FMA2(axy[o % 11], v, WP[k], axy[o % 11]);
                            ap[o % 11] = fmaf(WGs[k], pm, ap[o % 11]);
                        }
                    }
                }
                // output o = m-10 is complete: retire to smem
                if (m >= 10) {
                    const int o = m - 10;
                    vxy[o][c] = axy[o % 11];
                    vp [o][c] = ap [o % 11];
                }
            }
        } else {
            #pragma unroll
            for (int o = 0; o < TH; o++) { vxy[o][c] = 0ull; vp[o][c] = 0.0f; }
        }
    }
    __syncthreads();

    // ---- phase 2: horizontal FIR from smem + SSIM: 512 items, 4 rounds ----
    // item = (row r of 32, colgroup o of 16); 8 outputs, reads 18 cols.
    const float C1 = 0.0001f, C2 = 0.0009f;
    float lsum = 0.0f;
    #pragma unroll 1
    for (int i = tid; i < TH * (TW / 8); i += NT) {
        const int r  = i & 31;
        const int c0 = (i >> 5) * 8;

        unsigned long long acc2[8];
        float accp[8];
        #pragma unroll
        for (int j = 0; j < 8; j++) { acc2[j] = 0ull; accp[j] = 0.0f; }

        #pragma unroll
        for (int m = 0; m < 18; m++) {
            unsigned long long v = vxy[r][c0 + m];   // LDS.64 feeds FMA2 directly
            float pm = vp[r][c0 + m];
            #pragma unroll
            for (int j = 0; j < 8; j++) {
                const int k = m - j;
                if (k >= 0 && k <= 10) {
                    FMA2(acc2[j], v, WP[k], acc2[j]);
                    accp[j] = fmaf(WGs[k], pm, accp[j]);
                }
            }
        }
        #pragma unroll
        for (int j = 0; j < 8; j++) {
            float mu1, mu2;
            UNPK(mu1, mu2, acc2[j]);
            float m12 = mu1 * mu2;
            float sig = accp[j] - m12;
            float sq  = mu1 * mu1 + mu2 * mu2;
            float num = (2.0f * m12 + C1) * (2.0f * sig + C2);
            float den = (sq + C1) * (sq + C2);
            lsum += __fdividef(num, den);
        }
    }

    // ---------------- block reduction (128 threads, 4 warps) ----------------
    #pragma unroll
    for (int off = 16; off > 0; off >>= 1)
        lsum += __shfl_xor_sync(0xFFFFFFFFu, lsum, off);
    if ((tid & 31) == 0) wsum[tid >> 5] = lsum;
    __syncthreads();
    if (tid == 0) {
        float v = wsum[0] + wsum[1] + wsum[2] + wsum[3];
        int bid = blockIdx.x + GX * (blockIdx.y + GY * blockIdx.z);
        g_partials[bid] = v;
        __threadfence();
        unsigned int ticket = atomicAdd(&g_count, 1u);
        s_last = (ticket == NBLK - 1);
    }
    __syncthreads();

    // ---------------- last block: final reduction ----------------
    if (s_last) {
        float s = 0.0f;
        #pragma unroll 4
        for (int i = tid; i < NBLK; i += NT)
            s += *((volatile float*)&g_partials[i]);
        #pragma unroll
        for (int off = 16; off > 0; off >>= 1)
            s += __shfl_xor_sync(0xFFFFFFFFu, s, off);
        __syncthreads();
        if ((tid & 31) == 0) wsum[tid >> 5] = s;
        __syncthreads();
        if (tid == 0) {
            out[0]  = (wsum[0] + wsum[1] + wsum[2] + wsum[3]) * (1.0f / 8388608.0f);
            g_count = 0;
        }
    }
}

extern "C" void kernel_launch(void* const* d_in, const int* in_sizes, int n_in,
                              void* d_out, int out_size)
{
    (void)in_sizes; (void)n_in; (void)out_size;
    const float* X_gt   = (const float*)d_in[0];
    const float* X_pred = (const float*)d_in[1];
    float* out = (float*)d_out;

    dim3 grid(GX, GY, GZ);
    ssim_fused_kernel<<<grid, NT>>>(X_gt, X_pred, out);
}